// round 1
// baseline (speedup 1.0000x reference)
#include <cuda_runtime.h>

// Problem constants (fixed shapes for this problem)
constexpr int   Nn   = 8192;
constexpr int   TPB  = 256;
constexpr int   F4PT = Nn / (4 * TPB);   // 8 float4 per thread

// Scratch: compressed labels (values 0..127 fit in a byte). Static device
// array -> no allocation.
__device__ unsigned char g_labels[Nn];

// ---------------------------------------------------------------------------
// Pre-kernel: convert targets (int64 OR int32, auto-detected) -> uint8.
// Detection: if dtype is int64 (little-endian), every odd 32-bit word is the
// high half of a small label == 0. If int32, odd words are labels themselves
// (some nonzero w.h.p.). Probe only the first n words (safe for both widths).
// ---------------------------------------------------------------------------
__global__ void convert_labels_kernel(const unsigned int* __restrict__ traw, int n)
{
    __shared__ int s_or;
    int t = threadIdx.x;
    if (t == 0) s_or = 0;
    __syncthreads();

    unsigned int acc = 0;
    for (int i = 2 * t + 1; i < n; i += 2 * blockDim.x)
        acc |= traw[i];
    if (acc) atomicOr(&s_or, 1);
    __syncthreads();

    bool is64 = (s_or == 0);
    for (int i = t; i < n; i += blockDim.x) {
        unsigned int v = is64 ? traw[2 * i] : traw[i];
        g_labels[i] = (unsigned char)v;
    }
}

// ---------------------------------------------------------------------------
// Per-element math: shared exp for softplus + sigmoid, numerically stable.
//   pos (same label):  x = -2 s     loss = softplus(x), grad = sigmoid(x) * (-2/pos_cnt)
//   neg (diff label):  x = 40 s     loss = softplus(x), grad = sigmoid(x) * (40/neg_cnt)
//   s = sim - 0.5 ; pos pair additionally requires sim < 1 (else both zero)
// ---------------------------------------------------------------------------
__device__ __forceinline__ void elem(float sv, bool same, float row_valid,
                                     float gsp, float gsn,
                                     float& L, float& G)
{
    float s = sv - 0.5f;
    float x = same ? (-2.0f * s) : (40.0f * s);
    float a = fabsf(x);
    float e = __expf(-a);                 // in (0,1], never overflows
    float r = __fdividef(1.0f, 1.0f + e); // 1/(1+e)  (MUFU.RCP path)
    float sg = (x >= 0.0f) ? r : (e * r); // sigmoid(x), no cancellation
    float sp = fmaxf(x, 0.0f) - __logf(r);// max(x,0) + log1p(e)
    float valid = (same && sv >= 1.0f) ? 0.0f : 1.0f;
    L = sp * valid * row_valid;
    G = sg * (same ? gsp : gsn) * valid;  // row_valid folded into gsp/gsn
}

__global__ void __launch_bounds__(TPB)
binomial_kernel(const float* __restrict__ sim,
                float* __restrict__ out_loss,
                float* __restrict__ out_grad)
{
    __shared__ unsigned char lab_s[Nn];   // 8 KB
    __shared__ int s_same, s_pos;

    const int t   = threadIdx.x;
    const int row = blockIdx.x;

    if (t == 0) { s_same = 0; s_pos = 0; }

    // Cooperative label broadcast: 8192 B = 512 x int4
    {
        const int4* src = (const int4*)g_labels;
        int4*       dst = (int4*)lab_s;
        dst[t]       = src[t];
        dst[t + TPB] = src[t + TPB];
    }

    // Load the whole row into registers (batched LDG.128 -> high MLP)
    const float4* rp = (const float4*)(sim + (size_t)row * Nn);
    float4 v[F4PT];
#pragma unroll
    for (int k = 0; k < F4PT; ++k)
        v[k] = rp[t + k * TPB];

    __syncthreads();

    const unsigned int myl4 = (unsigned int)lab_s[row] * 0x01010101u;

    // ---- pass 1: counts ----
    int cnt_same = 0, cnt_pos = 0;
    unsigned int eqm[F4PT];
#pragma unroll
    for (int k = 0; k < F4PT; ++k) {
        unsigned int l4 = ((const unsigned int*)lab_s)[t + k * TPB];
        unsigned int eq = __vcmpeq4(l4, myl4);     // 0xFF per matching byte
        eqm[k] = eq;
        cnt_same += __popc(eq);
        unsigned int lt = 0;
        lt |= (v[k].x < 1.0f) ? 0x000000FFu : 0u;
        lt |= (v[k].y < 1.0f) ? 0x0000FF00u : 0u;
        lt |= (v[k].z < 1.0f) ? 0x00FF0000u : 0u;
        lt |= (v[k].w < 1.0f) ? 0xFF000000u : 0u;
        cnt_pos += __popc(eq & lt);
    }
    cnt_same >>= 3;  // popc counted 8 bits per matching byte
    cnt_pos  >>= 3;

#pragma unroll
    for (int o = 16; o; o >>= 1) {
        cnt_same += __shfl_down_sync(0xffffffffu, cnt_same, o);
        cnt_pos  += __shfl_down_sync(0xffffffffu, cnt_pos,  o);
    }
    if ((t & 31) == 0) {
        atomicAdd(&s_same, cnt_same);
        atomicAdd(&s_pos,  cnt_pos);
    }
    __syncthreads();

    const int   same_cnt  = s_same;
    const int   pos_cnt   = s_pos;
    const int   neg_raw   = Nn - same_cnt;
    const float row_valid = (neg_raw > 0) ? 1.0f : 0.0f;
    const float gsp = -2.0f * row_valid / (float)max(pos_cnt, 1);
    const float gsn = 40.0f * row_valid / (float)max(neg_raw, 1);

    // ---- pass 2: compute + store ----
    float4* lo = (float4*)(out_loss + (size_t)row * Nn);
    float4* gr = (float4*)(out_grad + (size_t)row * Nn);
#pragma unroll
    for (int k = 0; k < F4PT; ++k) {
        unsigned int eq = eqm[k];
        float4 L, G;
        elem(v[k].x, (eq & 0x000000FFu) != 0, row_valid, gsp, gsn, L.x, G.x);
        elem(v[k].y, (eq & 0x0000FF00u) != 0, row_valid, gsp, gsn, L.y, G.y);
        elem(v[k].z, (eq & 0x00FF0000u) != 0, row_valid, gsp, gsn, L.z, G.z);
        elem(v[k].w, (eq & 0xFF000000u) != 0, row_valid, gsp, gsn, L.w, G.w);
        int idx = t + k * TPB;
        lo[idx] = L;
        gr[idx] = G;
    }
}

// ---------------------------------------------------------------------------
extern "C" void kernel_launch(void* const* d_in, const int* in_sizes, int n_in,
                              void* d_out, int out_size)
{
    const float*        sim  = (const float*)d_in[0];
    const unsigned int* traw = (const unsigned int*)d_in[1];
    float*              out  = (float*)d_out;

    const int    n  = in_sizes[1];          // 8192 rows
    const size_t nn = (size_t)in_sizes[0];  // N*N  (loss|grad split point)

    convert_labels_kernel<<<1, TPB>>>(traw, n);
    binomial_kernel<<<n, TPB>>>(sim, out, out + nn);
}

// round 4
// speedup vs baseline: 1.0259x; 1.0259x over previous
#include <cuda_runtime.h>

constexpr int Nn  = 8192;
constexpr int TPB = 512;
constexpr int F4  = Nn / (4 * TPB);   // 4 float4 per thread

// Compressed labels (0..127 fit in a byte). Static device array -> no allocation.
__device__ unsigned char g_labels[Nn];

// ---------------------------------------------------------------------------
// cp.async helpers (LDGSTS.128, L1-bypass)
// ---------------------------------------------------------------------------
__device__ __forceinline__ void cp_async16(void* smem_ptr, const void* gmem_ptr)
{
    unsigned s = (unsigned)__cvta_generic_to_shared(smem_ptr);
    asm volatile("cp.async.cg.shared.global [%0], [%1], 16;\n" :: "r"(s), "l"(gmem_ptr));
}

// ---------------------------------------------------------------------------
// Pre-kernel: targets (int64 OR int32, auto-detected) -> uint8. Parallelized
// across 32 blocks; each block scans odd 32-bit words (strided) to detect
// int64 (all high halves zero) vs int32 (some odd-position label nonzero).
// Only the first n words are probed (safe for both widths).
// ---------------------------------------------------------------------------
__global__ void convert_labels_kernel(const unsigned int* __restrict__ traw, int n)
{
    __shared__ int s_or;
    int t = threadIdx.x;
    if (t == 0) s_or = 0;
    __syncthreads();

    unsigned int acc = 0;
    for (int i = 2 * t + 1; i < n; i += 2 * blockDim.x)
        acc |= traw[i];
    if (acc) atomicOr(&s_or, 1);
    __syncthreads();

    bool is64 = (s_or == 0);
    int base = blockIdx.x * blockDim.x;
    int i = base + t;
    if (i < n) {
        unsigned int v = is64 ? traw[2 * i] : traw[i];
        g_labels[i] = (unsigned char)v;
    }
}

// ---------------------------------------------------------------------------
// Per-element math, shared exp for softplus + sigmoid, numerically stable.
//   pos (same label, sim<1):  x = -2 s    neg (diff label):  x = 40 s
//   loss = softplus(x), grad = sigmoid(x) * scale / count
// ---------------------------------------------------------------------------
__device__ __forceinline__ void elem(float sv, bool same, float row_valid,
                                     float gsp, float gsn,
                                     float& L, float& G)
{
    float s = sv - 0.5f;
    float x = same ? (-2.0f * s) : (40.0f * s);
    float a = fabsf(x);
    float e = __expf(-a);                  // (0,1], never overflows
    float r = __fdividef(1.0f, 1.0f + e);  // 1/(1+e)
    float sg = (x >= 0.0f) ? r : (e * r);  // sigmoid(x), no cancellation
    float sp = fmaxf(x, 0.0f) - __logf(r); // max(x,0) + log1p(e)
    float valid = (same && sv >= 1.0f) ? 0.0f : 1.0f;
    L = sp * valid * row_valid;
    G = sg * (same ? gsp : gsn) * valid;   // row_valid folded into gsp/gsn
}

__global__ void __launch_bounds__(TPB)
binomial_kernel(const float* __restrict__ sim,
                float* __restrict__ out_loss,
                float* __restrict__ out_grad)
{
    __shared__ float4 row_s[Nn / 4];      // 32 KB row cache
    __shared__ int s_same, s_pos;

    const int t   = threadIdx.x;
    const int row = blockIdx.x;

    if (t == 0) { s_same = 0; s_pos = 0; }

    // Async bulk copy of the row into smem (L1-bypass, no register cache)
    const float4* rp = (const float4*)(sim + (size_t)row * Nn);
#pragma unroll
    for (int k = 0; k < F4; ++k)
        cp_async16(&row_s[t + k * TPB], &rp[t + k * TPB]);
    asm volatile("cp.async.commit_group;\n");

    const unsigned int myl4 =
        (unsigned int)__ldg(&g_labels[row]) * 0x01010101u;
    const unsigned int* __restrict__ lab4 = (const unsigned int*)g_labels;

    asm volatile("cp.async.wait_group 0;\n" ::: "memory");
    __syncthreads();

    // ---- pass 1: counts (labels via L1-resident LDG, values via LDS) ----
    int cnt_same = 0, cnt_pos = 0;
#pragma unroll
    for (int k = 0; k < F4; ++k) {
        int idx = t + k * TPB;
        unsigned int eq = __vcmpeq4(__ldg(&lab4[idx]), myl4); // 0xFF per match
        float4 v = row_s[idx];
        cnt_same += __popc(eq);
        unsigned int lt = 0;
        lt |= (v.x < 1.0f) ? 0x000000FFu : 0u;
        lt |= (v.y < 1.0f) ? 0x0000FF00u : 0u;
        lt |= (v.z < 1.0f) ? 0x00FF0000u : 0u;
        lt |= (v.w < 1.0f) ? 0xFF000000u : 0u;
        cnt_pos += __popc(eq & lt);
    }
    cnt_same >>= 3;   // popc counted 8 bits per matching byte
    cnt_pos  >>= 3;

#pragma unroll
    for (int o = 16; o; o >>= 1) {
        cnt_same += __shfl_down_sync(0xffffffffu, cnt_same, o);
        cnt_pos  += __shfl_down_sync(0xffffffffu, cnt_pos,  o);
    }
    if ((t & 31) == 0) {
        atomicAdd(&s_same, cnt_same);
        atomicAdd(&s_pos,  cnt_pos);
    }
    __syncthreads();

    const int   same_cnt  = s_same;
    const int   pos_cnt   = s_pos;
    const int   neg_raw   = Nn - same_cnt;
    const float row_valid = (neg_raw > 0) ? 1.0f : 0.0f;
    const float gsp = -2.0f * row_valid / (float)max(pos_cnt, 1);
    const float gsn = 40.0f * row_valid / (float)max(neg_raw, 1);

    // ---- pass 2: compute + streaming stores ----
    float4* lo = (float4*)(out_loss + (size_t)row * Nn);
    float4* gr = (float4*)(out_grad + (size_t)row * Nn);
#pragma unroll
    for (int k = 0; k < F4; ++k) {
        int idx = t + k * TPB;
        unsigned int eq = __vcmpeq4(__ldg(&lab4[idx]), myl4);
        float4 v = row_s[idx];
        float4 L, G;
        elem(v.x, (eq & 0x000000FFu) != 0, row_valid, gsp, gsn, L.x, G.x);
        elem(v.y, (eq & 0x0000FF00u) != 0, row_valid, gsp, gsn, L.y, G.y);
        elem(v.z, (eq & 0x00FF0000u) != 0, row_valid, gsp, gsn, L.z, G.z);
        elem(v.w, (eq & 0xFF000000u) != 0, row_valid, gsp, gsn, L.w, G.w);
        __stcs(&lo[idx], L);
        __stcs(&gr[idx], G);
    }
}

// ---------------------------------------------------------------------------
extern "C" void kernel_launch(void* const* d_in, const int* in_sizes, int n_in,
                              void* d_out, int out_size)
{
    const float*        sim  = (const float*)d_in[0];
    const unsigned int* traw = (const unsigned int*)d_in[1];
    float*              out  = (float*)d_out;

    const int    n  = in_sizes[1];          // 8192 rows
    const size_t nn = (size_t)in_sizes[0];  // N*N  (loss | grad split point)

    convert_labels_kernel<<<(n + 255) / 256, 256>>>(traw, n);
    binomial_kernel<<<n, TPB>>>(sim, out, out + nn);
}